// round 5
// baseline (speedup 1.0000x reference)
#include <cuda_runtime.h>
#include <cuda_bf16.h>
#include <cstdint>

// Problem constants: NUM=32, NUM_TOP=32, COBJ=4, B=300, D=256, H=256, L=128, patch 4x4

typedef unsigned long long ull;

// Scratch: hidden activations (+b1), transposed [side][n][h(256)][a(128)]
__device__ __align__(16) float g_Ht[2 * 32 * 256 * 128];   // 8.4 MB

// ---------------- packed f32x2 helpers ----------------
__device__ __forceinline__ ull pk2(float x, float y) {
    ull r;
    asm("mov.b64 %0, {%1, %2};" : "=l"(r)
        : "r"(__float_as_uint(x)), "r"(__float_as_uint(y)));
    return r;
}
__device__ __forceinline__ void upk2(ull v, float& x, float& y) {
    unsigned int lo, hi;
    asm("mov.b64 {%0, %1}, %2;" : "=r"(lo), "=r"(hi) : "l"(v));
    x = __uint_as_float(lo); y = __uint_as_float(hi);
}
__device__ __forceinline__ ull fma2(ull a, ull b, ull c) {
    ull d;
    asm("fma.rn.f32x2 %0, %1, %2, %3;" : "=l"(d) : "l"(a), "l"(b), "l"(c));
    return d;
}
__device__ __forceinline__ ull add2(ull a, ull b) {
    ull d;
    asm("add.rn.f32x2 %0, %1, %2;" : "=l"(d) : "l"(a), "l"(b));
    return d;
}

// ---------------- Phase 1: gather + GEMM (+b1), store transposed ----------
// 256 blocks: [n(32)] x [side(2)] x [quarter(4) of 32 rows], 256 threads.
// Block computes C[32 rows][256 cols] = A_gathered[32,256] @ W[256,256].
// A stored in shared dup-transposed: Asd[k][2r] = Asd[k][2r+1] = A[r][k],
// so the packed-dup FFMA2 'a' operand is a single broadcast LDS.64.
__global__ __launch_bounds__(256)
void k_gemm(const float* __restrict__ fea,
            const int* __restrict__ ind0, const int* __restrict__ ind1,
            const float* __restrict__ W1a, const float* __restrict__ W1b,
            const float* __restrict__ b1)
{
    const int id   = blockIdx.x;
    const int n    = id >> 3;
    const int side = (id >> 2) & 1;
    const int q    = id & 3;
    const int* __restrict__ ind = side ? ind1 : ind0;
    const float* __restrict__ W = side ? W1b : W1a;

    __shared__ __align__(16) float Asd[32][64];    // dup-transposed A tile, 8KB
    __shared__ __align__(16) float Bs[32][256];    // 32KB
    __shared__ int rowOff[32];

    const int tid = threadIdx.x;
    if (tid < 32) {
        int a = q * 32 + tid;
        int t = a >> 2, c = a & 3;
        int b = ind[(n * 32 + t) * 4 + c];
        rowOff[tid] = ((n * 8 + side * 4 + c) * 300 + b) * 256;
    }
    __syncthreads();

    const int rowg = tid >> 5;      // warp id 0..7 -> rows 4w..4w+3
    const int cA   = (tid & 31) * 4; // cols cA..cA+3 and 128+cA..128+cA+3

    // 4 rows x 8 cols = 4x4 packed f32x2 accumulators (lanes = col pair)
    ull acc2[4][4];
#pragma unroll
    for (int u = 0; u < 4; u++)
#pragma unroll
        for (int p = 0; p < 4; p++) acc2[u][p] = 0ull;

    const int arow = tid >> 3;       // 0..31 for A loads
    const int aq   = tid & 7;

    for (int kt = 0; kt < 8; kt++) {
        const int d0 = kt * 32;
        // A tile: 32 rows x 32 k, one float4 per thread, dup-store transposed
        {
            float4 v = *(const float4*)(fea + rowOff[arow] + d0 + aq * 4);
            const int r2 = 2 * arow;
            *(float2*)&Asd[aq * 4 + 0][r2] = make_float2(v.x, v.x);
            *(float2*)&Asd[aq * 4 + 1][r2] = make_float2(v.y, v.y);
            *(float2*)&Asd[aq * 4 + 2][r2] = make_float2(v.z, v.z);
            *(float2*)&Asd[aq * 4 + 3][r2] = make_float2(v.w, v.w);
        }
        // B tile: 32x256 = 2048 float4, 8 per thread
#pragma unroll
        for (int p = 0; p < 8; p++) {
            int f4 = tid + p * 256;
            int kr = f4 >> 6, qq = f4 & 63;
            *(float4*)&Bs[kr][qq * 4] = *(const float4*)(W + (d0 + kr) * 256 + qq * 4);
        }
        __syncthreads();

#pragma unroll 4
        for (int k = 0; k < 32; k++) {
            float4 bb0 = *(float4*)&Bs[k][cA];
            float4 bb1 = *(float4*)&Bs[k][128 + cA];
            ull pb0 = pk2(bb0.x, bb0.y);
            ull pb1 = pk2(bb0.z, bb0.w);
            ull pb2 = pk2(bb1.x, bb1.y);
            ull pb3 = pk2(bb1.z, bb1.w);
            const float* ap = &Asd[k][8 * rowg];
#pragma unroll
            for (int u = 0; u < 4; u++) {
                ull pa = *(const ull*)(ap + 2 * u);   // (A[r],A[r]) broadcast
                acc2[u][0] = fma2(pa, pb0, acc2[u][0]);
                acc2[u][1] = fma2(pa, pb1, acc2[u][1]);
                acc2[u][2] = fma2(pa, pb2, acc2[u][2]);
                acc2[u][3] = fma2(pa, pb3, acc2[u][3]);
            }
        }
        __syncthreads();
    }

    // Unpack, add b1, store transposed: g_Ht[side][n][col][a]
    float accf[4][8];
#pragma unroll
    for (int u = 0; u < 4; u++)
#pragma unroll
        for (int p = 0; p < 4; p++)
            upk2(acc2[u][p], accf[u][2 * p], accf[u][2 * p + 1]);

    int cols[8];
#pragma unroll
    for (int p = 0; p < 4; p++) { cols[p] = cA + p; cols[4 + p] = 128 + cA + p; }

    float* base = g_Ht + (size_t)(side * 32 + n) * 32768 + q * 32 + 4 * rowg;
#pragma unroll
    for (int j = 0; j < 8; j++) {
        const int col = cols[j];
        const float bias = b1[col];
        float4 v = make_float4(accf[0][j] + bias, accf[1][j] + bias,
                               accf[2][j] + bias, accf[3][j] + bias);
        *(float4*)(base + (size_t)col * 128) = v;
    }
}

// ---------------- Phase 2: pairwise relu-relation + fused 4x4 patch sum ---
// 128 blocks: [n(32)] x [atile(4) of 32 a-rows], 1024 threads.
// 4 thread-groups of 256; group g handles h-chunks {2g, 2g+1} with private
// smem tiles; partials combined in-block at the end.
// Thread (i,j) in a group: one 4x4 output patch; packed f32x2 adds,
// scalar FMNMX relu, packed reduction tree.
__global__ __launch_bounds__(1024, 1)
void k_pair(const float* __restrict__ W2, const float* __restrict__ b2,
            float* __restrict__ out, int write_pairs)
{
    extern __shared__ __align__(16) float sm[];
    const int n     = blockIdx.x >> 2;
    const int atile = blockIdx.x & 3;
    const int a0    = atile * 32;
    const int tid   = threadIdx.x;
    const int g     = tid >> 8;     // group 0..3
    const int t     = tid & 255;
    const int i     = t >> 5;       // patch row 0..7
    const int j     = t & 31;       // patch col 0..31

    float* S0d = sm + g * 2048;            // [32 h][64] dup: S0d[h][2a]=S0d[h][2a+1]
    float* S1  = sm + 8192 + g * 4096;     // [32 h][128]
    float* ws  = sm + 24576 + g * 32;
    float* red = sm + 24704;               // [1024]

    const float* __restrict__ H0 = g_Ht + (size_t)n * 32768;
    const float* __restrict__ H1 = g_Ht + (size_t)(32 + n) * 32768;

    float acc = 0.f;
#pragma unroll
    for (int cc = 0; cc < 2; cc++) {
        const int h0 = (g * 2 + cc) * 32;
        if (t < 32) ws[t] = W2[h0 + t];
        {   // S0 dup-tile: 32h x 32a, one float4 per thread
            int h = t >> 3, qf = t & 7;
            float4 v = *(const float4*)(H0 + (size_t)(h0 + h) * 128 + a0 + 4 * qf);
            float* d = &S0d[h * 64 + 8 * qf];
            *(float4*)(d)     = make_float4(v.x, v.x, v.y, v.y);
            *(float4*)(d + 4) = make_float4(v.z, v.z, v.w, v.w);
        }
#pragma unroll
        for (int p = 0; p < 4; p++) {  // S1: 32h x 128b, 4 float4 per thread
            int f4 = t + p * 256;
            int h = f4 >> 5, qf = f4 & 31;
            *(float4*)&S1[h * 128 + 4 * qf] =
                *(const float4*)(H1 + (size_t)(h0 + h) * 128 + 4 * qf);
        }
        __syncthreads();

#pragma unroll 2
        for (int h = 0; h < 32; h++) {
            const float w = ws[h];
            const float* ap = &S0d[h * 64 + 8 * i];
            ull pa0 = *(const ull*)(ap + 0);    // (A0,A0) broadcast LDS.64
            ull pa1 = *(const ull*)(ap + 2);
            ull pa2 = *(const ull*)(ap + 4);
            ull pa3 = *(const ull*)(ap + 6);
            float4 b = *(float4*)&S1[h * 128 + 4 * j];
            ull pb0 = pk2(b.x, b.y);
            ull pb1 = pk2(b.z, b.w);

            ull s0 = add2(pa0, pb0), s1 = add2(pa0, pb1);
            ull s2 = add2(pa1, pb0), s3 = add2(pa1, pb1);
            ull s4 = add2(pa2, pb0), s5 = add2(pa2, pb1);
            ull s6 = add2(pa3, pb0), s7 = add2(pa3, pb1);

            float x, y;
            float r0,r1,r2,r3,r4,r5,r6,r7,r8,r9,r10,r11,r12,r13,r14,r15;
            upk2(s0, x, y); r0  = fmaxf(x, 0.f); r1  = fmaxf(y, 0.f);
            upk2(s1, x, y); r2  = fmaxf(x, 0.f); r3  = fmaxf(y, 0.f);
            upk2(s2, x, y); r4  = fmaxf(x, 0.f); r5  = fmaxf(y, 0.f);
            upk2(s3, x, y); r6  = fmaxf(x, 0.f); r7  = fmaxf(y, 0.f);
            upk2(s4, x, y); r8  = fmaxf(x, 0.f); r9  = fmaxf(y, 0.f);
            upk2(s5, x, y); r10 = fmaxf(x, 0.f); r11 = fmaxf(y, 0.f);
            upk2(s6, x, y); r12 = fmaxf(x, 0.f); r13 = fmaxf(y, 0.f);
            upk2(s7, x, y); r14 = fmaxf(x, 0.f); r15 = fmaxf(y, 0.f);

            ull t0 = pk2(r0,  r1),  t1 = pk2(r2,  r3);
            ull t2 = pk2(r4,  r5),  t3 = pk2(r6,  r7);
            ull t4 = pk2(r8,  r9),  t5 = pk2(r10, r11);
            ull t6 = pk2(r12, r13), t7 = pk2(r14, r15);
            ull u0 = add2(t0, t1), u1 = add2(t2, t3);
            ull u2 = add2(t4, t5), u3 = add2(t6, t7);
            ull v0 = add2(u0, u1), v1 = add2(u2, u3);
            ull z  = add2(v0, v1);
            float zl, zh; upk2(z, zl, zh);
            acc = fmaf(zl + zh, w, acc);
        }
        __syncthreads();
    }

    red[tid] = acc;
    __syncthreads();
    if (tid < 256) {
        float val = red[tid] + red[tid + 256] + red[tid + 512] + red[tid + 768]
                  + 16.0f * b2[0];
        const int m = atile * 8 + i;
        const int p = m * 32 + j;
        out[n * 1024 + p] = val;
        if (write_pairs) {
            float* pr = out + 32768 + ((size_t)n * 1024 + p) * 2;
            pr[0] = (float)m;
            pr[1] = (float)j;
        }
    }
}

static const int K_PAIR_SMEM = (24704 + 1024) * 4;   // 102912 bytes

extern "C" void kernel_launch(void* const* d_in, const int* in_sizes, int n_in,
                              void* d_out, int out_size)
{
    (void)in_sizes;
    const float* fea  = (const float*)d_in[0];
    const int*   ind0 = (const int*)d_in[1];
    const int*   ind1 = (const int*)d_in[2];
    const int base = (n_in >= 9) ? 4 : 3;   // 'k' may be a materialized input
    const float* W1a = (const float*)d_in[base + 0];
    const float* W1b = (const float*)d_in[base + 1];
    const float* b1  = (const float*)d_in[base + 2];
    const float* W2  = (const float*)d_in[base + 3];
    const float* b2  = (const float*)d_in[base + 4];
    float* out = (float*)d_out;

    const int write_pairs = (out_size >= 3 * 32768) ? 1 : 0;

    cudaFuncSetAttribute(k_pair, cudaFuncAttributeMaxDynamicSharedMemorySize,
                         K_PAIR_SMEM);

    k_gemm<<<256, 256>>>(fea, ind0, ind1, W1a, W1b, b1);
    k_pair<<<128, 1024, K_PAIR_SMEM>>>(W2, b2, out, write_pairs);
}

// round 6
// speedup vs baseline: 1.0708x; 1.0708x over previous
#include <cuda_runtime.h>
#include <cuda_bf16.h>
#include <cstdint>

// Problem constants: NUM=32, NUM_TOP=32, COBJ=4, B=300, D=256, H=256, L=128, patch 4x4

typedef unsigned long long ull;

// Scratch: hidden activations (+b1), transposed [side][n][h(256)][a(128)]
__device__ __align__(16) float g_Ht[2 * 32 * 256 * 128];   // 8.4 MB

// ---------------- packed f32x2 helpers ----------------
__device__ __forceinline__ ull pk2(float x, float y) {
    ull r;
    asm("mov.b64 %0, {%1, %2};" : "=l"(r)
        : "r"(__float_as_uint(x)), "r"(__float_as_uint(y)));
    return r;
}
__device__ __forceinline__ void upk2(ull v, float& x, float& y) {
    unsigned int lo, hi;
    asm("mov.b64 {%0, %1}, %2;" : "=r"(lo), "=r"(hi) : "l"(v));
    x = __uint_as_float(lo); y = __uint_as_float(hi);
}
__device__ __forceinline__ ull fma2(ull a, ull b, ull c) {
    ull d;
    asm("fma.rn.f32x2 %0, %1, %2, %3;" : "=l"(d) : "l"(a), "l"(b), "l"(c));
    return d;
}
__device__ __forceinline__ ull add2(ull a, ull b) {
    ull d;
    asm("add.rn.f32x2 %0, %1, %2;" : "=l"(d) : "l"(a), "l"(b));
    return d;
}

// ---------------- Phase 1: gather + GEMM (+b1), store transposed ----------
// 128 blocks: [n(32)] x [side(2)] x [half(2) of 64 rows], 512 threads.
// Block computes C[64 rows][256 cols] = A_gathered[64,256] @ W[256,256].
// Warp w (0..15) owns rows 4w..4w+3; each lane owns cols lane*4..+3 and
// 128+lane*4..+3. A is dup-stored transposed in smem so the packed-dup FFMA2
// 'a' operand is a single broadcast LDS.64; B pairs read directly as
// ulonglong2 (adjacent floats == packed pair, zero MOVs).
#define ASTRIDE 130   // pad to break STS bank conflicts on dup stores

__global__ __launch_bounds__(512)
void k_gemm(const float* __restrict__ fea,
            const int* __restrict__ ind0, const int* __restrict__ ind1,
            const float* __restrict__ W1a, const float* __restrict__ W1b,
            const float* __restrict__ b1)
{
    const int id   = blockIdx.x;
    const int n    = id >> 2;
    const int side = (id >> 1) & 1;
    const int half = id & 1;
    const int* __restrict__ ind = side ? ind1 : ind0;
    const float* __restrict__ W = side ? W1b : W1a;

    __shared__ __align__(16) float Asd[32][ASTRIDE];  // dup-transposed A, ~16.6KB
    __shared__ __align__(16) float Bs[32][256];       // 32KB
    __shared__ int rowOff[64];

    const int tid = threadIdx.x;
    if (tid < 64) {
        int a = half * 64 + tid;
        int t = a >> 2, c = a & 3;
        int b = ind[(n * 32 + t) * 4 + c];
        rowOff[tid] = ((n * 8 + side * 4 + c) * 300 + b) * 256;
    }
    __syncthreads();

    const int w    = tid >> 5;        // warp 0..15 -> rows 4w..4w+3
    const int lane = tid & 31;
    const int cA   = lane * 4;        // cols cA..cA+3 and 128+cA..128+cA+3

    // 4 rows x 8 cols = 4x4 packed f32x2 accumulators
    ull acc2[4][4];
#pragma unroll
    for (int u = 0; u < 4; u++)
#pragma unroll
        for (int p = 0; p < 4; p++) acc2[u][p] = 0ull;

    const int arow = tid >> 3;        // 0..63 for A loads
    const int aq   = tid & 7;

    for (int kt = 0; kt < 8; kt++) {
        const int d0 = kt * 32;
        // A tile: 64 rows x 32 k = 512 float4, one per thread, dup-store transposed
        {
            float4 v = *(const float4*)(fea + rowOff[arow] + d0 + aq * 4);
            const int r2 = 2 * arow;
            *(float2*)&Asd[aq * 4 + 0][r2] = make_float2(v.x, v.x);
            *(float2*)&Asd[aq * 4 + 1][r2] = make_float2(v.y, v.y);
            *(float2*)&Asd[aq * 4 + 2][r2] = make_float2(v.z, v.z);
            *(float2*)&Asd[aq * 4 + 3][r2] = make_float2(v.w, v.w);
        }
        // B tile: 32x256 = 2048 float4, 4 per thread
#pragma unroll
        for (int p = 0; p < 4; p++) {
            int f4 = tid + p * 512;
            int kr = f4 >> 6, qq = f4 & 63;
            *(float4*)&Bs[kr][qq * 4] = *(const float4*)(W + (d0 + kr) * 256 + qq * 4);
        }
        __syncthreads();

#pragma unroll 4
        for (int k = 0; k < 32; k++) {
            ulonglong2 bA = *(const ulonglong2*)&Bs[k][cA];        // (c0,c1),(c2,c3)
            ulonglong2 bB = *(const ulonglong2*)&Bs[k][128 + cA];  // (c128..c131)
            const float* ap = &Asd[k][8 * w];
#pragma unroll
            for (int u = 0; u < 4; u++) {
                ull pa = *(const ull*)(ap + 2 * u);   // (A[r],A[r]) broadcast
                acc2[u][0] = fma2(pa, bA.x, acc2[u][0]);
                acc2[u][1] = fma2(pa, bA.y, acc2[u][1]);
                acc2[u][2] = fma2(pa, bB.x, acc2[u][2]);
                acc2[u][3] = fma2(pa, bB.y, acc2[u][3]);
            }
        }
        __syncthreads();
    }

    // Unpack, add b1, store transposed: g_Ht[side][n][col][a]
    float accf[4][8];
#pragma unroll
    for (int u = 0; u < 4; u++)
#pragma unroll
        for (int p = 0; p < 4; p++)
            upk2(acc2[u][p], accf[u][2 * p], accf[u][2 * p + 1]);

    int cols[8];
#pragma unroll
    for (int p = 0; p < 4; p++) { cols[p] = cA + p; cols[4 + p] = 128 + cA + p; }

    float* base = g_Ht + (size_t)(side * 32 + n) * 32768 + half * 64 + 4 * w;
#pragma unroll
    for (int j = 0; j < 8; j++) {
        const int col = cols[j];
        const float bias = b1[col];
        float4 v = make_float4(accf[0][j] + bias, accf[1][j] + bias,
                               accf[2][j] + bias, accf[3][j] + bias);
        *(float4*)(base + (size_t)col * 128) = v;
    }
}

// ---------------- Phase 2: pairwise relu-relation + fused 4x4 patch sum ---
// 128 blocks: [n(32)] x [atile(4) of 32 a-rows], 1024 threads.
// 4 thread-groups of 256; group g handles h-chunks {2g, 2g+1} with private
// smem tiles; partials combined in-block at the end.
__global__ __launch_bounds__(1024, 1)
void k_pair(const float* __restrict__ W2, const float* __restrict__ b2,
            float* __restrict__ out, int write_pairs)
{
    extern __shared__ __align__(16) float sm[];
    const int n     = blockIdx.x >> 2;
    const int atile = blockIdx.x & 3;
    const int a0    = atile * 32;
    const int tid   = threadIdx.x;
    const int g     = tid >> 8;     // group 0..3
    const int t     = tid & 255;
    const int i     = t >> 5;       // patch row 0..7
    const int j     = t & 31;       // patch col 0..31

    float* S0d = sm + g * 2048;            // [32 h][64] dup: S0d[h][2a]=S0d[h][2a+1]
    float* S1  = sm + 8192 + g * 4096;     // [32 h][128]
    float* ws  = sm + 24576 + g * 32;
    float* red = sm + 24704;               // [1024]

    const float* __restrict__ H0 = g_Ht + (size_t)n * 32768;
    const float* __restrict__ H1 = g_Ht + (size_t)(32 + n) * 32768;

    float acc = 0.f;
#pragma unroll
    for (int cc = 0; cc < 2; cc++) {
        const int h0 = (g * 2 + cc) * 32;
        if (t < 32) ws[t] = W2[h0 + t];
        {   // S0 dup-tile: 32h x 32a, one float4 per thread
            int h = t >> 3, qf = t & 7;
            float4 v = *(const float4*)(H0 + (size_t)(h0 + h) * 128 + a0 + 4 * qf);
            float* d = &S0d[h * 64 + 8 * qf];
            *(float4*)(d)     = make_float4(v.x, v.x, v.y, v.y);
            *(float4*)(d + 4) = make_float4(v.z, v.z, v.w, v.w);
        }
#pragma unroll
        for (int p = 0; p < 4; p++) {  // S1: 32h x 128b, 4 float4 per thread
            int f4 = t + p * 256;
            int h = f4 >> 5, qf = f4 & 31;
            *(float4*)&S1[h * 128 + 4 * qf] =
                *(const float4*)(H1 + (size_t)(h0 + h) * 128 + 4 * qf);
        }
        __syncthreads();

#pragma unroll 2
        for (int h = 0; h < 32; h++) {
            const float w = ws[h];
            const float* ap = &S0d[h * 64 + 8 * i];
            ull pa0 = *(const ull*)(ap + 0);    // (A0,A0) broadcast LDS.64
            ull pa1 = *(const ull*)(ap + 2);
            ull pa2 = *(const ull*)(ap + 4);
            ull pa3 = *(const ull*)(ap + 6);
            ulonglong2 bp = *(const ulonglong2*)&S1[h * 128 + 4 * j];
            ull pb0 = bp.x;                      // (B0,B1) — already packed
            ull pb1 = bp.y;                      // (B2,B3)

            ull s0 = add2(pa0, pb0), s1 = add2(pa0, pb1);
            ull s2 = add2(pa1, pb0), s3 = add2(pa1, pb1);
            ull s4 = add2(pa2, pb0), s5 = add2(pa2, pb1);
            ull s6 = add2(pa3, pb0), s7 = add2(pa3, pb1);

            float x, y;
            float r0,r1,r2,r3,r4,r5,r6,r7,r8,r9,r10,r11,r12,r13,r14,r15;
            upk2(s0, x, y); r0  = fmaxf(x, 0.f); r1  = fmaxf(y, 0.f);
            upk2(s1, x, y); r2  = fmaxf(x, 0.f); r3  = fmaxf(y, 0.f);
            upk2(s2, x, y); r4  = fmaxf(x, 0.f); r5  = fmaxf(y, 0.f);
            upk2(s3, x, y); r6  = fmaxf(x, 0.f); r7  = fmaxf(y, 0.f);
            upk2(s4, x, y); r8  = fmaxf(x, 0.f); r9  = fmaxf(y, 0.f);
            upk2(s5, x, y); r10 = fmaxf(x, 0.f); r11 = fmaxf(y, 0.f);
            upk2(s6, x, y); r12 = fmaxf(x, 0.f); r13 = fmaxf(y, 0.f);
            upk2(s7, x, y); r14 = fmaxf(x, 0.f); r15 = fmaxf(y, 0.f);

            ull t0 = pk2(r0,  r1),  t1 = pk2(r2,  r3);
            ull t2 = pk2(r4,  r5),  t3 = pk2(r6,  r7);
            ull t4 = pk2(r8,  r9),  t5 = pk2(r10, r11);
            ull t6 = pk2(r12, r13), t7 = pk2(r14, r15);
            ull u0 = add2(t0, t1), u1 = add2(t2, t3);
            ull u2 = add2(t4, t5), u3 = add2(t6, t7);
            ull v0 = add2(u0, u1), v1 = add2(u2, u3);
            ull z  = add2(v0, v1);
            float zl, zh; upk2(z, zl, zh);
            acc = fmaf(zl + zh, w, acc);
        }
        __syncthreads();
    }

    red[tid] = acc;
    __syncthreads();
    if (tid < 256) {
        float val = red[tid] + red[tid + 256] + red[tid + 512] + red[tid + 768]
                  + 16.0f * b2[0];
        const int m = atile * 8 + i;
        const int p = m * 32 + j;
        out[n * 1024 + p] = val;
        if (write_pairs) {
            float* pr = out + 32768 + ((size_t)n * 1024 + p) * 2;
            pr[0] = (float)m;
            pr[1] = (float)j;
        }
    }
}

static const int K_PAIR_SMEM = (24704 + 1024) * 4;   // 102912 bytes

extern "C" void kernel_launch(void* const* d_in, const int* in_sizes, int n_in,
                              void* d_out, int out_size)
{
    (void)in_sizes;
    const float* fea  = (const float*)d_in[0];
    const int*   ind0 = (const int*)d_in[1];
    const int*   ind1 = (const int*)d_in[2];
    const int base = (n_in >= 9) ? 4 : 3;   // 'k' may be a materialized input
    const float* W1a = (const float*)d_in[base + 0];
    const float* W1b = (const float*)d_in[base + 1];
    const float* b1  = (const float*)d_in[base + 2];
    const float* W2  = (const float*)d_in[base + 3];
    const float* b2  = (const float*)d_in[base + 4];
    float* out = (float*)d_out;

    const int write_pairs = (out_size >= 3 * 32768) ? 1 : 0;

    cudaFuncSetAttribute(k_pair, cudaFuncAttributeMaxDynamicSharedMemorySize,
                         K_PAIR_SMEM);

    k_gemm<<<128, 512>>>(fea, ind0, ind1, W1a, W1b, b1);
    k_pair<<<128, 1024, K_PAIR_SMEM>>>(W2, b2, out, write_pairs);
}

// round 12
// speedup vs baseline: 1.0780x; 1.0067x over previous
#include <cuda_runtime.h>
#include <cuda_bf16.h>
#include <cstdint>

// Problem constants: NUM=32, NUM_TOP=32, COBJ=4, B=300, D=256, H=256, L=128, patch 4x4

typedef unsigned long long ull;

// Scratch: hidden activations (+b1), transposed [side][n][h(256)][a(128)]
__device__ __align__(16) float g_Ht[2 * 32 * 256 * 128];   // 8.4 MB

// ---------------- packed f32x2 helpers ----------------
__device__ __forceinline__ ull pk2(float x, float y) {
    ull r;
    asm("mov.b64 %0, {%1, %2};" : "=l"(r)
        : "r"(__float_as_uint(x)), "r"(__float_as_uint(y)));
    return r;
}
__device__ __forceinline__ void upk2(ull v, float& x, float& y) {
    unsigned int lo, hi;
    asm("mov.b64 {%0, %1}, %2;" : "=r"(lo), "=r"(hi) : "l"(v));
    x = __uint_as_float(lo); y = __uint_as_float(hi);
}
__device__ __forceinline__ ull fma2(ull a, ull b, ull c) {
    ull d;
    asm("fma.rn.f32x2 %0, %1, %2, %3;" : "=l"(d) : "l"(a), "l"(b), "l"(c));
    return d;
}
__device__ __forceinline__ ull add2(ull a, ull b) {
    ull d;
    asm("add.rn.f32x2 %0, %1, %2;" : "=l"(d) : "l"(a), "l"(b));
    return d;
}

// ---------------- Phase 1: gather + GEMM (+b1), store transposed ----------
// 128 blocks: [n(32)] x [side(2)] x [half(2) of 64 rows], 512 threads.
// Block computes C[64 rows][256 cols] = A_gathered[64,256] @ W[256,256].
// 16 warps: warp w -> rows 8*(w&7)..+7, col-half (w>>3) (128 cols), lane owns
// 4 cols. Per warp-k: 4 broadcast LDS.128 of dup-A pairs + 1 LDS.128 of B
// (already packed col pairs) + 16 FFMA2. Double-buffered smem, reg prefetch.
#define ASTR 132                      // dup-A row stride (16B aligned, 4-way STS ok)
#define A_TILE (32 * ASTR)            // 4224 floats
#define B_TILE (32 * 256)             // 8192 floats

__global__ __launch_bounds__(512)
void k_gemm(const float* __restrict__ fea,
            const int* __restrict__ ind0, const int* __restrict__ ind1,
            const float* __restrict__ W1a, const float* __restrict__ W1b,
            const float* __restrict__ b1)
{
    extern __shared__ __align__(16) float sg[];
    float* AsD = sg;                  // 2 buffers x A_TILE
    float* BsD = sg + 2 * A_TILE;     // 2 buffers x B_TILE
    __shared__ int rowOff[64];

    const int id   = blockIdx.x;
    const int n    = id >> 2;
    const int side = (id >> 1) & 1;
    const int half = id & 1;
    const int* __restrict__ ind = side ? ind1 : ind0;
    const float* __restrict__ W = side ? W1b : W1a;

    const int tid = threadIdx.x;
    if (tid < 64) {
        int a = half * 64 + tid;
        int t = a >> 2, c = a & 3;
        int b = ind[(n * 32 + t) * 4 + c];
        rowOff[tid] = ((n * 8 + side * 4 + c) * 300 + b) * 256;
    }
    __syncthreads();

    const int w    = tid >> 5;
    const int lane = tid & 31;
    const int w8   = w & 7;           // row group: rows 8*w8..8*w8+7
    const int ch   = w >> 3;          // col half
    const int cOff = ch * 128 + lane * 4;

    const int ar = tid >> 3;          // A-load row 0..63
    const int aq = tid & 7;           // A-load k-quad 0..7

    // ---- prefetch tile 0 ----
    float4 av = *(const float4*)(fea + rowOff[ar] + aq * 4);
    float4 bv[4];
#pragma unroll
    for (int p = 0; p < 4; p++) {
        int f4 = tid + p * 512;
        int kr = f4 >> 6, qq = f4 & 63;
        bv[p] = *(const float4*)(W + kr * 256 + qq * 4);
    }
    // store tile 0 into buffer 0
    {
        float* Ad = AsD;
        const int r2 = 2 * ar;
        *(float2*)&Ad[(aq * 4 + 0) * ASTR + r2] = make_float2(av.x, av.x);
        *(float2*)&Ad[(aq * 4 + 1) * ASTR + r2] = make_float2(av.y, av.y);
        *(float2*)&Ad[(aq * 4 + 2) * ASTR + r2] = make_float2(av.z, av.z);
        *(float2*)&Ad[(aq * 4 + 3) * ASTR + r2] = make_float2(av.w, av.w);
        float* Bd = BsD;
#pragma unroll
        for (int p = 0; p < 4; p++) {
            int f4 = tid + p * 512;
            int kr = f4 >> 6, qq = f4 & 63;
            *(float4*)&Bd[kr * 256 + qq * 4] = bv[p];
        }
    }
    __syncthreads();

    ull acc[8][2];                    // 8 rows x 2 col-pairs
#pragma unroll
    for (int u = 0; u < 8; u++) { acc[u][0] = 0ull; acc[u][1] = 0ull; }

#pragma unroll
    for (int kt = 0; kt < 8; kt++) {
        // prefetch next tile into registers
        if (kt < 7) {
            const int d0 = (kt + 1) * 32;
            av = *(const float4*)(fea + rowOff[ar] + d0 + aq * 4);
#pragma unroll
            for (int p = 0; p < 4; p++) {
                int f4 = tid + p * 512;
                int kr = f4 >> 6, qq = f4 & 63;
                bv[p] = *(const float4*)(W + (d0 + kr) * 256 + qq * 4);
            }
        }
        const float* A = AsD + (kt & 1) * A_TILE;
        const float* B = BsD + (kt & 1) * B_TILE;

#pragma unroll 4
        for (int k = 0; k < 32; k++) {
            ulonglong2 bp = *(const ulonglong2*)&B[k * 256 + cOff];
            const float* ap = &A[k * ASTR + 16 * w8];
            ulonglong2 a01 = *(const ulonglong2*)(ap + 0);   // dup rows 0,1
            ulonglong2 a23 = *(const ulonglong2*)(ap + 4);   // dup rows 2,3
            ulonglong2 a45 = *(const ulonglong2*)(ap + 8);   // dup rows 4,5
            ulonglong2 a67 = *(const ulonglong2*)(ap + 12);  // dup rows 6,7
            acc[0][0] = fma2(a01.x, bp.x, acc[0][0]);
            acc[0][1] = fma2(a01.x, bp.y, acc[0][1]);
            acc[1][0] = fma2(a01.y, bp.x, acc[1][0]);
            acc[1][1] = fma2(a01.y, bp.y, acc[1][1]);
            acc[2][0] = fma2(a23.x, bp.x, acc[2][0]);
            acc[2][1] = fma2(a23.x, bp.y, acc[2][1]);
            acc[3][0] = fma2(a23.y, bp.x, acc[3][0]);
            acc[3][1] = fma2(a23.y, bp.y, acc[3][1]);
            acc[4][0] = fma2(a45.x, bp.x, acc[4][0]);
            acc[4][1] = fma2(a45.x, bp.y, acc[4][1]);
            acc[5][0] = fma2(a45.y, bp.x, acc[5][0]);
            acc[5][1] = fma2(a45.y, bp.y, acc[5][1]);
            acc[6][0] = fma2(a67.x, bp.x, acc[6][0]);
            acc[6][1] = fma2(a67.x, bp.y, acc[6][1]);
            acc[7][0] = fma2(a67.y, bp.x, acc[7][0]);
            acc[7][1] = fma2(a67.y, bp.y, acc[7][1]);
        }

        if (kt < 7) {
            float* Ad = AsD + ((kt + 1) & 1) * A_TILE;
            const int r2 = 2 * ar;
            *(float2*)&Ad[(aq * 4 + 0) * ASTR + r2] = make_float2(av.x, av.x);
            *(float2*)&Ad[(aq * 4 + 1) * ASTR + r2] = make_float2(av.y, av.y);
            *(float2*)&Ad[(aq * 4 + 2) * ASTR + r2] = make_float2(av.z, av.z);
            *(float2*)&Ad[(aq * 4 + 3) * ASTR + r2] = make_float2(av.w, av.w);
            float* Bd = BsD + ((kt + 1) & 1) * B_TILE;
#pragma unroll
            for (int p = 0; p < 4; p++) {
                int f4 = tid + p * 512;
                int kr = f4 >> 6, qq = f4 & 63;
                *(float4*)&Bd[kr * 256 + qq * 4] = bv[p];
            }
            __syncthreads();
        }
    }

    // Epilogue: unpack, add b1, store transposed g_Ht[side][n][col][row]
    float accf[8][4];
#pragma unroll
    for (int u = 0; u < 8; u++) {
        upk2(acc[u][0], accf[u][0], accf[u][1]);
        upk2(acc[u][1], accf[u][2], accf[u][3]);
    }
    float* base = g_Ht + (size_t)(side * 32 + n) * 32768 + half * 64 + 8 * w8;
#pragma unroll
    for (int cc = 0; cc < 4; cc++) {
        const int col = cOff + cc;
        const float bias = b1[col];
        float4 v0 = make_float4(accf[0][cc] + bias, accf[1][cc] + bias,
                                accf[2][cc] + bias, accf[3][cc] + bias);
        float4 v1 = make_float4(accf[4][cc] + bias, accf[5][cc] + bias,
                                accf[6][cc] + bias, accf[7][cc] + bias);
        float* dst = base + (size_t)col * 128;
        *(float4*)dst       = v0;
        *(float4*)(dst + 4) = v1;
    }
}

static const int K_GEMM_SMEM = (2 * A_TILE + 2 * B_TILE) * 4;   // 99328 B

// ---------------- Phase 2: pairwise relu-relation + fused 4x4 patch sum ---
// 128 blocks: [n(32)] x [atile(4) of 32 a-rows], 1024 threads.
// 4 groups of 256; group g handles h-chunks {2g,2g+1} with private smem tiles.
// 4 packed f32x2 accumulators (no reduction tree) for ILP; dup-packed W2.
__global__ __launch_bounds__(1024, 1)
void k_pair(const float* __restrict__ W2, const float* __restrict__ b2,
            float* __restrict__ out, int write_pairs)
{
    extern __shared__ __align__(16) float sm[];
    const int n     = blockIdx.x >> 2;
    const int atile = blockIdx.x & 3;
    const int a0    = atile * 32;
    const int tid   = threadIdx.x;
    const int g     = tid >> 8;     // group 0..3
    const int t     = tid & 255;
    const int i     = t >> 5;       // patch row 0..7
    const int j     = t & 31;       // patch col 0..31

    float* S0d = sm + g * 2048;            // [32 h][64] dup pairs
    float* S1  = sm + 8192 + g * 4096;     // [32 h][128]
    float* wsd = sm + 24576 + g * 64;      // [32 h] dup-packed W2
    float* red = sm + 24832;               // [1024]

    const float* __restrict__ H0 = g_Ht + (size_t)n * 32768;
    const float* __restrict__ H1 = g_Ht + (size_t)(32 + n) * 32768;

    ull pacc[4];
#pragma unroll
    for (int p = 0; p < 4; p++) pacc[p] = 0ull;

#pragma unroll
    for (int cc = 0; cc < 2; cc++) {
        const int h0 = (g * 2 + cc) * 32;
        if (t < 32) {
            float wv = W2[h0 + t];
            *(float2*)&wsd[2 * t] = make_float2(wv, wv);
        }
        {   // S0 dup-tile: 32h x 32a, one float4 per thread
            int h = t >> 3, qf = t & 7;
            float4 v = *(const float4*)(H0 + (size_t)(h0 + h) * 128 + a0 + 4 * qf);
            float* d = &S0d[h * 64 + 8 * qf];
            *(float4*)(d)     = make_float4(v.x, v.x, v.y, v.y);
            *(float4*)(d + 4) = make_float4(v.z, v.z, v.w, v.w);
        }
#pragma unroll
        for (int p = 0; p < 4; p++) {  // S1: 32h x 128b, 4 float4 per thread
            int f4 = t + p * 256;
            int h = f4 >> 5, qf = f4 & 31;
            *(float4*)&S1[h * 128 + 4 * qf] =
                *(const float4*)(H1 + (size_t)(h0 + h) * 128 + 4 * qf);
        }
        __syncthreads();

#pragma unroll 2
        for (int h = 0; h < 32; h++) {
            ull w2 = *(const ull*)&wsd[2 * h];   // (w,w) broadcast
            const float* ap = &S0d[h * 64 + 8 * i];
            ull pa0 = *(const ull*)(ap + 0);
            ull pa1 = *(const ull*)(ap + 2);
            ull pa2 = *(const ull*)(ap + 4);
            ull pa3 = *(const ull*)(ap + 6);
            ulonglong2 bp = *(const ulonglong2*)&S1[h * 128 + 4 * j];
            ull pb0 = bp.x, pb1 = bp.y;

            ull s0 = add2(pa0, pb0), s1 = add2(pa0, pb1);
            ull s2 = add2(pa1, pb0), s3 = add2(pa1, pb1);
            ull s4 = add2(pa2, pb0), s5 = add2(pa2, pb1);
            ull s6 = add2(pa3, pb0), s7 = add2(pa3, pb1);

            float x, y;
            float r0,r1,r2,r3,r4,r5,r6,r7,r8,r9,r10,r11,r12,r13,r14,r15;
            upk2(s0, x, y); r0  = fmaxf(x, 0.f); r1  = fmaxf(y, 0.f);
            upk2(s1, x, y); r2  = fmaxf(x, 0.f); r3  = fmaxf(y, 0.f);
            upk2(s2, x, y); r4  = fmaxf(x, 0.f); r5  = fmaxf(y, 0.f);
            upk2(s3, x, y); r6  = fmaxf(x, 0.f); r7  = fmaxf(y, 0.f);
            upk2(s4, x, y); r8  = fmaxf(x, 0.f); r9  = fmaxf(y, 0.f);
            upk2(s5, x, y); r10 = fmaxf(x, 0.f); r11 = fmaxf(y, 0.f);
            upk2(s6, x, y); r12 = fmaxf(x, 0.f); r13 = fmaxf(y, 0.f);
            upk2(s7, x, y); r14 = fmaxf(x, 0.f); r15 = fmaxf(y, 0.f);

            pacc[0] = fma2(pk2(r0,  r1),  w2, pacc[0]);
            pacc[1] = fma2(pk2(r2,  r3),  w2, pacc[1]);
            pacc[2] = fma2(pk2(r4,  r5),  w2, pacc[2]);
            pacc[3] = fma2(pk2(r6,  r7),  w2, pacc[3]);
            pacc[0] = fma2(pk2(r8,  r9),  w2, pacc[0]);
            pacc[1] = fma2(pk2(r10, r11), w2, pacc[1]);
            pacc[2] = fma2(pk2(r12, r13), w2, pacc[2]);
            pacc[3] = fma2(pk2(r14, r15), w2, pacc[3]);
        }
        __syncthreads();
    }

    ull ps = add2(add2(pacc[0], pacc[1]), add2(pacc[2], pacc[3]));
    float zl, zh; upk2(ps, zl, zh);
    red[tid] = zl + zh;
    __syncthreads();
    if (tid < 256) {
        float val = red[tid] + red[tid + 256] + red[tid + 512] + red[tid + 768]
                  + 16.0f * b2[0];
        const int m = atile * 8 + i;
        const int p = m * 32 + j;
        out[n * 1024 + p] = val;
        if (write_pairs) {
            float* pr = out + 32768 + ((size_t)n * 1024 + p) * 2;
            pr[0] = (float)m;
            pr[1] = (float)j;
        }
    }
}

static const int K_PAIR_SMEM = (24832 + 1024) * 4;   // 103424 B

extern "C" void kernel_launch(void* const* d_in, const int* in_sizes, int n_in,
                              void* d_out, int out_size)
{
    (void)in_sizes;
    const float* fea  = (const float*)d_in[0];
    const int*   ind0 = (const int*)d_in[1];
    const int*   ind1 = (const int*)d_in[2];
    const int base = (n_in >= 9) ? 4 : 3;   // 'k' may be a materialized input
    const float* W1a = (const float*)d_in[base + 0];
    const float* W1b = (const float*)d_in[base + 1];
    const float* b1  = (const float*)d_in[base + 2];
    const float* W2  = (const float*)d_in[base + 3];
    const float* b2  = (const float*)d_in[base + 4];
    float* out = (float*)d_out;

    const int write_pairs = (out_size >= 3 * 32768) ? 1 : 0;

    cudaFuncSetAttribute(k_gemm, cudaFuncAttributeMaxDynamicSharedMemorySize,
                         K_GEMM_SMEM);
    cudaFuncSetAttribute(k_pair, cudaFuncAttributeMaxDynamicSharedMemorySize,
                         K_PAIR_SMEM);

    k_gemm<<<128, 512, K_GEMM_SMEM>>>(fea, ind0, ind1, W1a, W1b, b1);
    k_pair<<<128, 1024, K_PAIR_SMEM>>>(W2, b2, out, write_pairs);
}

// round 17
// speedup vs baseline: 1.4162x; 1.3138x over previous
#include <cuda_runtime.h>
#include <cuda_bf16.h>
#include <cstdint>

// Problem constants: NUM=32, NUM_TOP=32, COBJ=4, B=300, D=256, H=256, L=128, patch 4x4

typedef unsigned long long ull;

// Scratch: hidden activations (+b1), transposed [side][n][h(256)][a(128)]
__device__ __align__(16) float g_Ht[2 * 32 * 256 * 128];            // 8.4 MB
// W transposed to [N][K] ("col-major B" for mma.row.col) + bf16x2 split
__device__ __align__(16) __nv_bfloat16 g_Wt0[2 * 256 * 256];
__device__ __align__(16) __nv_bfloat16 g_Wt1[2 * 256 * 256];

// ---------------- packed f32x2 helpers (k_pair) ----------------
__device__ __forceinline__ ull pk2(float x, float y) {
    ull r;
    asm("mov.b64 %0, {%1, %2};" : "=l"(r)
        : "r"(__float_as_uint(x)), "r"(__float_as_uint(y)));
    return r;
}
__device__ __forceinline__ void upk2(ull v, float& x, float& y) {
    unsigned int lo, hi;
    asm("mov.b64 {%0, %1}, %2;" : "=r"(lo), "=r"(hi) : "l"(v));
    x = __uint_as_float(lo); y = __uint_as_float(hi);
}
__device__ __forceinline__ ull fma2(ull a, ull b, ull c) {
    ull d;
    asm("fma.rn.f32x2 %0, %1, %2, %3;" : "=l"(d) : "l"(a), "l"(b), "l"(c));
    return d;
}
__device__ __forceinline__ ull add2(ull a, ull b) {
    ull d;
    asm("add.rn.f32x2 %0, %1, %2;" : "=l"(d) : "l"(a), "l"(b));
    return d;
}

// ---------------- warp-MMA helpers (sm_80+ path, compiles for sm_103) -----
__device__ __forceinline__ uint32_t smem_to_u32(const void* p) {
    uint32_t a;
    asm("{ .reg .u64 t; cvta.to.shared.u64 t, %1; cvt.u32.u64 %0, t; }"
        : "=r"(a) : "l"(p));
    return a;
}
#define LDSM_X4(R0, R1, R2, R3, ADDR) \
    asm volatile("ldmatrix.sync.aligned.m8n8.x4.shared.b16 {%0,%1,%2,%3}, [%4];" \
        : "=r"(R0), "=r"(R1), "=r"(R2), "=r"(R3) : "r"(ADDR))
#define MMA_BF16(D, A, B0_, B1_) \
    asm volatile("mma.sync.aligned.m16n8k16.row.col.f32.bf16.bf16.f32 " \
        "{%0,%1,%2,%3}, {%4,%5,%6,%7}, {%8,%9}, {%0,%1,%2,%3};" \
        : "+f"((D)[0]), "+f"((D)[1]), "+f"((D)[2]), "+f"((D)[3]) \
        : "r"((A)[0]), "r"((A)[1]), "r"((A)[2]), "r"((A)[3]), \
          "r"(B0_), "r"(B1_))

// bf16x2 split of 8 floats -> two uint4 (8 bf16 each)
__device__ __forceinline__ void cvt_split8(const float4 va, const float4 vb,
                                           uint4& o0, uint4& o1) {
    float f[8] = {va.x, va.y, va.z, va.w, vb.x, vb.y, vb.z, vb.w};
    __nv_bfloat16 lo[8], hi[8];
#pragma unroll
    for (int e = 0; e < 8; e++) {
        lo[e] = __float2bfloat16_rn(f[e]);
        hi[e] = __float2bfloat16_rn(f[e] - __bfloat162float(lo[e]));
    }
    o0 = *(uint4*)lo;
    o1 = *(uint4*)hi;
}

// ---------------- W prep: transpose + bf16x2 split ------------------------
__global__ __launch_bounds__(256)
void k_prepW(const float* __restrict__ W1a, const float* __restrict__ W1b)
{
    int gid = blockIdx.x * 256 + threadIdx.x;      // 131072 total
    int side = gid >> 16;
    int rem  = gid & 65535;
    int nn   = rem >> 8;
    int kk   = rem & 255;
    const float* __restrict__ W = side ? W1b : W1a;
    float v = W[kk * 256 + nn];
    __nv_bfloat16 h0 = __float2bfloat16_rn(v);
    g_Wt0[side * 65536 + nn * 256 + kk] = h0;
    g_Wt1[side * 65536 + nn * 256 + kk] =
        __float2bfloat16_rn(v - __bfloat162float(h0));
}

// ---------------- Phase 1: gather + bf16x2 HMMA GEMM ----------------------
// 128 blocks: (n, side, nhalf). 256 threads (8 warps).
// Block computes C[128 rows][128 cols] = A[128,256] @ W[:, nhalf*128..+128].
// K staged in 4 chunks of 64 (A gathered fp32->bf16 split; B from g_Wt0/1).
// Warp (w>>1 = m-tile of 32, w&1 = n-tile of 64); 3 split passes into the
// same fp32 accumulators. Epilogue transposes through smem, adds b1.
#define KSTR 72                          // smem k-stride (bf16) per row
static constexpr int A0_OFF = 0;                 // 128*72*2 = 18432 B
static constexpr int A1_OFF = 18432;
static constexpr int B0_OFF = 36864;
static constexpr int B1_OFF = 55296;
static constexpr int GEMM_SMEM = 73728;          // CT (67584 B) reuses [0..)

__global__ __launch_bounds__(256)
void k_gemm(const float* __restrict__ fea,
            const int* __restrict__ ind0, const int* __restrict__ ind1,
            const float* __restrict__ b1)
{
    extern __shared__ __align__(16) char smc[];
    __nv_bfloat16* A0 = (__nv_bfloat16*)(smc + A0_OFF);
    __nv_bfloat16* A1 = (__nv_bfloat16*)(smc + A1_OFF);
    __nv_bfloat16* B0 = (__nv_bfloat16*)(smc + B0_OFF);
    __nv_bfloat16* B1 = (__nv_bfloat16*)(smc + B1_OFF);
    const uint32_t sb = smem_to_u32(smc);

    const int bidx = blockIdx.x;
    const int n    = bidx >> 2;
    const int side = (bidx >> 1) & 1;
    const int nh   = bidx & 1;
    const int* __restrict__ ind = side ? ind1 : ind0;

    const int tid  = threadIdx.x;
    const int warp = tid >> 5;
    const int lane = tid & 31;

    // my gather row (two threads per row, split k halves)
    const int r    = tid >> 1;
    const int koff = (tid & 1) * 32;
    const int t_ = r >> 2, c_ = r & 3;
    const int bb = ind[(n * 32 + t_) * 4 + c_];
    const float* __restrict__ srcRow =
        fea + ((size_t)((n * 8 + side * 4 + c_) * 300 + bb)) * 256;
    const __nv_bfloat16* __restrict__ gW0 =
        g_Wt0 + side * 65536 + (size_t)(nh * 128 + r) * 256;
    const __nv_bfloat16* __restrict__ gW1 =
        g_Wt1 + side * 65536 + (size_t)(nh * 128 + r) * 256;

    // warp tiling
    const int warp_m = (warp >> 1) * 32;
    const int warp_n = (warp & 1) * 64;
    // ldmatrix lane addressing
    const int aRow = lane & 15;
    const int aK   = (lane >> 4) * 8;
    const int bRow = (lane & 7) + ((lane >> 4) << 3);
    const int bK   = ((lane >> 3) & 1) * 8;

    float acc[2][8][4];
#pragma unroll
    for (int mt = 0; mt < 2; mt++)
#pragma unroll
        for (int nt = 0; nt < 8; nt++)
#pragma unroll
            for (int e = 0; e < 4; e++) acc[mt][nt][e] = 0.f;

    for (int kc = 0; kc < 4; kc++) {
        const int k0 = kc * 64;
        // A gather + split: 32 floats per thread
        {
            const float4* s = (const float4*)(srcRow + k0 + koff);
            __nv_bfloat16* p0 = A0 + r * KSTR + koff;
            __nv_bfloat16* p1 = A1 + r * KSTR + koff;
#pragma unroll
            for (int q = 0; q < 4; q++) {
                uint4 o0, o1;
                cvt_split8(s[2 * q], s[2 * q + 1], o0, o1);
                *(uint4*)(p0 + q * 8) = o0;
                *(uint4*)(p1 + q * 8) = o1;
            }
        }
        // B tiles: 32 bf16 per thread per split
        {
            const uint4* s0 = (const uint4*)(gW0 + k0 + koff);
            const uint4* s1 = (const uint4*)(gW1 + k0 + koff);
            __nv_bfloat16* p0 = B0 + r * KSTR + koff;
            __nv_bfloat16* p1 = B1 + r * KSTR + koff;
#pragma unroll
            for (int q = 0; q < 4; q++) {
                *(uint4*)(p0 + q * 8) = s0[q];
                *(uint4*)(p1 + q * 8) = s1[q];
            }
        }
        __syncthreads();

#pragma unroll
        for (int ks = 0; ks < 4; ks++) {
            const int kcol = ks * 16;
            uint32_t a0f[2][4], a1f[2][4];
#pragma unroll
            for (int mt = 0; mt < 2; mt++) {
                uint32_t off = ((warp_m + mt * 16 + aRow) * KSTR + kcol + aK) * 2;
                LDSM_X4(a0f[mt][0], a0f[mt][1], a0f[mt][2], a0f[mt][3],
                        sb + A0_OFF + off);
                LDSM_X4(a1f[mt][0], a1f[mt][1], a1f[mt][2], a1f[mt][3],
                        sb + A1_OFF + off);
            }
            uint32_t b0f[4][4], b1f[4][4];
#pragma unroll
            for (int nt = 0; nt < 4; nt++) {
                uint32_t off = ((warp_n + nt * 16 + bRow) * KSTR + kcol + bK) * 2;
                LDSM_X4(b0f[nt][0], b0f[nt][1], b0f[nt][2], b0f[nt][3],
                        sb + B0_OFF + off);
                LDSM_X4(b1f[nt][0], b1f[nt][1], b1f[nt][2], b1f[nt][3],
                        sb + B1_OFF + off);
            }
#pragma unroll
            for (int mt = 0; mt < 2; mt++) {
#pragma unroll
                for (int nt = 0; nt < 4; nt++) {
                    // n low 8 (regs 0,1) and n high 8 (regs 2,3)
                    MMA_BF16(acc[mt][nt * 2],     a0f[mt], b0f[nt][0], b0f[nt][1]);
                    MMA_BF16(acc[mt][nt * 2],     a0f[mt], b1f[nt][0], b1f[nt][1]);
                    MMA_BF16(acc[mt][nt * 2],     a1f[mt], b0f[nt][0], b0f[nt][1]);
                    MMA_BF16(acc[mt][nt * 2 + 1], a0f[mt], b0f[nt][2], b0f[nt][3]);
                    MMA_BF16(acc[mt][nt * 2 + 1], a0f[mt], b1f[nt][2], b1f[nt][3]);
                    MMA_BF16(acc[mt][nt * 2 + 1], a1f[mt], b0f[nt][2], b0f[nt][3]);
                }
            }
        }
        __syncthreads();
    }

    // Epilogue: acc -> CT[col][row] (stride 132), then coalesced out (+b1)
    float* CT = (float*)smc;
    {
        const int lr = lane >> 2;
        const int lc = 2 * (lane & 3);
#pragma unroll
        for (int mt = 0; mt < 2; mt++) {
#pragma unroll
            for (int nt = 0; nt < 8; nt++) {
                int row = warp_m + mt * 16 + lr;
                int col = warp_n + nt * 8 + lc;
                CT[col * 132 + row]           = acc[mt][nt][0];
                CT[(col + 1) * 132 + row]     = acc[mt][nt][1];
                CT[col * 132 + row + 8]       = acc[mt][nt][2];
                CT[(col + 1) * 132 + row + 8] = acc[mt][nt][3];
            }
        }
    }
    __syncthreads();
    {
        const int col = tid >> 1;
        const int rh  = (tid & 1) * 64;
        const float bias = b1[nh * 128 + col];
        const float4* s = (const float4*)(CT + col * 132 + rh);
        float* dst = g_Ht + (size_t)(side * 32 + n) * 32768
                   + (size_t)(nh * 128 + col) * 128 + rh;
#pragma unroll
        for (int q = 0; q < 16; q++) {
            float4 v = s[q];
            v.x += bias; v.y += bias; v.z += bias; v.w += bias;
            ((float4*)dst)[q] = v;
        }
    }
}

// ---------------- Phase 2: pairwise relu-relation + fused 4x4 patch sum ---
// (unchanged: 128 blocks x 1024 threads, 4 groups x 2 h-chunks)
__global__ __launch_bounds__(1024, 1)
void k_pair(const float* __restrict__ W2, const float* __restrict__ b2,
            float* __restrict__ out, int write_pairs)
{
    extern __shared__ __align__(16) float sm[];
    const int n     = blockIdx.x >> 2;
    const int atile = blockIdx.x & 3;
    const int a0    = atile * 32;
    const int tid   = threadIdx.x;
    const int g     = tid >> 8;
    const int t     = tid & 255;
    const int i     = t >> 5;
    const int j     = t & 31;

    float* S0d = sm + g * 2048;
    float* S1  = sm + 8192 + g * 4096;
    float* wsd = sm + 24576 + g * 64;
    float* red = sm + 24832;

    const float* __restrict__ H0 = g_Ht + (size_t)n * 32768;
    const float* __restrict__ H1 = g_Ht + (size_t)(32 + n) * 32768;

    ull pacc[4];
#pragma unroll
    for (int p = 0; p < 4; p++) pacc[p] = 0ull;

#pragma unroll
    for (int cc = 0; cc < 2; cc++) {
        const int h0 = (g * 2 + cc) * 32;
        if (t < 32) {
            float wv = W2[h0 + t];
            *(float2*)&wsd[2 * t] = make_float2(wv, wv);
        }
        {
            int h = t >> 3, qf = t & 7;
            float4 v = *(const float4*)(H0 + (size_t)(h0 + h) * 128 + a0 + 4 * qf);
            float* d = &S0d[h * 64 + 8 * qf];
            *(float4*)(d)     = make_float4(v.x, v.x, v.y, v.y);
            *(float4*)(d + 4) = make_float4(v.z, v.z, v.w, v.w);
        }
#pragma unroll
        for (int p = 0; p < 4; p++) {
            int f4 = t + p * 256;
            int h = f4 >> 5, qf = f4 & 31;
            *(float4*)&S1[h * 128 + 4 * qf] =
                *(const float4*)(H1 + (size_t)(h0 + h) * 128 + 4 * qf);
        }
        __syncthreads();

#pragma unroll 2
        for (int h = 0; h < 32; h++) {
            ull w2 = *(const ull*)&wsd[2 * h];
            const float* ap = &S0d[h * 64 + 8 * i];
            ull pa0 = *(const ull*)(ap + 0);
            ull pa1 = *(const ull*)(ap + 2);
            ull pa2 = *(const ull*)(ap + 4);
            ull pa3 = *(const ull*)(ap + 6);
            ulonglong2 bp = *(const ulonglong2*)&S1[h * 128 + 4 * j];
            ull pb0 = bp.x, pb1 = bp.y;

            ull s0 = add2(pa0, pb0), s1 = add2(pa0, pb1);
            ull s2 = add2(pa1, pb0), s3 = add2(pa1, pb1);
            ull s4 = add2(pa2, pb0), s5 = add2(pa2, pb1);
            ull s6 = add2(pa3, pb0), s7 = add2(pa3, pb1);

            float x, y;
            float r0,r1,r2,r3,r4,r5,r6,r7,r8,r9,r10,r11,r12,r13,r14,r15;
            upk2(s0, x, y); r0  = fmaxf(x, 0.f); r1  = fmaxf(y, 0.f);
            upk2(s1, x, y); r2  = fmaxf(x, 0.f); r3  = fmaxf(y, 0.f);
            upk2(s2, x, y); r4  = fmaxf(x, 0.f); r5  = fmaxf(y, 0.f);
            upk2(s3, x, y); r6  = fmaxf(x, 0.f); r7  = fmaxf(y, 0.f);
            upk2(s4, x, y); r8  = fmaxf(x, 0.f); r9  = fmaxf(y, 0.f);
            upk2(s5, x, y); r10 = fmaxf(x, 0.f); r11 = fmaxf(y, 0.f);
            upk2(s6, x, y); r12 = fmaxf(x, 0.f); r13 = fmaxf(y, 0.f);
            upk2(s7, x, y); r14 = fmaxf(x, 0.f); r15 = fmaxf(y, 0.f);

            pacc[0] = fma2(pk2(r0,  r1),  w2, pacc[0]);
            pacc[1] = fma2(pk2(r2,  r3),  w2, pacc[1]);
            pacc[2] = fma2(pk2(r4,  r5),  w2, pacc[2]);
            pacc[3] = fma2(pk2(r6,  r7),  w2, pacc[3]);
            pacc[0] = fma2(pk2(r8,  r9),  w2, pacc[0]);
            pacc[1] = fma2(pk2(r10, r11), w2, pacc[1]);
            pacc[2] = fma2(pk2(r12, r13), w2, pacc[2]);
            pacc[3] = fma2(pk2(r14, r15), w2, pacc[3]);
        }
        __syncthreads();
    }

    ull ps = add2(add2(pacc[0], pacc[1]), add2(pacc[2], pacc[3]));
    float zl, zh; upk2(ps, zl, zh);
    red[tid] = zl + zh;
    __syncthreads();
    if (tid < 256) {
        float val = red[tid] + red[tid + 256] + red[tid + 512] + red[tid + 768]
                  + 16.0f * b2[0];
        const int m = atile * 8 + i;
        const int p = m * 32 + j;
        out[n * 1024 + p] = val;
        if (write_pairs) {
            float* pr = out + 32768 + ((size_t)n * 1024 + p) * 2;
            pr[0] = (float)m;
            pr[1] = (float)j;
        }
    }
}

static const int K_PAIR_SMEM = (24832 + 1024) * 4;   // 103424 B

extern "C" void kernel_launch(void* const* d_in, const int* in_sizes, int n_in,
                              void* d_out, int out_size)
{
    (void)in_sizes;
    const float* fea  = (const float*)d_in[0];
    const int*   ind0 = (const int*)d_in[1];
    const int*   ind1 = (const int*)d_in[2];
    const int base = (n_in >= 9) ? 4 : 3;   // 'k' may be a materialized input
    const float* W1a = (const float*)d_in[base + 0];
    const float* W1b = (const float*)d_in[base + 1];
    const float* b1  = (const float*)d_in[base + 2];
    const float* W2  = (const float*)d_in[base + 3];
    const float* b2  = (const float*)d_in[base + 4];
    float* out = (float*)d_out;

    const int write_pairs = (out_size >= 3 * 32768) ? 1 : 0;

    cudaFuncSetAttribute(k_gemm, cudaFuncAttributeMaxDynamicSharedMemorySize,
                         GEMM_SMEM);
    cudaFuncSetAttribute(k_pair, cudaFuncAttributeMaxDynamicSharedMemorySize,
                         K_PAIR_SMEM);

    k_prepW<<<512, 256>>>(W1a, W1b);
    k_gemm<<<128, 256, GEMM_SMEM>>>(fea, ind0, ind1, b1);
    k_pair<<<128, 1024, K_PAIR_SMEM>>>(W2, b2, out, write_pairs);
}